// round 5
// baseline (speedup 1.0000x reference)
#include <cuda_runtime.h>
#include <cstdint>

#define NSIDE 128
#define NPIX (12*NSIDE*NSIDE)   /* 196608 */
#define B 8
#define CIN 16
#define COUT 32
#define BC (B*CIN)              /* 128 */
#define TILE_P 32
#define CSTRIDE 132             /* 128 floats per pixel-chunk row + 4 pad (528B, 16B-mult) */
#define WS_FLOATS 4608
#define VB_FLOATS (2*TILE_P*CSTRIDE)          /* 8448 */
/* smem: weights + 2 chunk buffers + neigh table + 2 mbarriers (16B-aligned) */
#define NS_INTS (TILE_P*9)                    /* 288 */
#define SMEM_BYTES ((WS_FLOATS + VB_FLOATS)*4 + NS_INTS*4 + 32)

// scratch: transposed, zero-padded x  (pixel-major: xt[idx][c*8+b])
__device__ float g_xt[(NPIX + 1) * BC];

// ---------------------------------------------------------------------------
// Kernel A: transpose x [B][CIN][NPIX] -> xt [NPIX+1][c*8+b], row NPIX = zeros
// ---------------------------------------------------------------------------
__global__ void transpose_kernel(const float* __restrict__ x) {
    __shared__ float tile[BC * 33];
    const int tid  = threadIdx.x;
    const int idx0 = blockIdx.x * 32;

    #pragma unroll
    for (int i = tid; i < BC * 32; i += 256) {
        int r  = i >> 5;            // r = b*16 + c
        int j  = i & 31;
        int cc = (r & 15) * 8 + (r >> 4);
        tile[cc * 33 + j] = x[r * NPIX + idx0 + j];
    }
    __syncthreads();
    #pragma unroll
    for (int i = tid; i < BC * 32; i += 256) {
        int j  = i >> 7;
        int cc = i & 127;
        g_xt[(idx0 + j) * BC + cc] = tile[cc * 33 + j];
    }
    if (blockIdx.x == 0 && tid < BC) g_xt[NPIX * BC + tid] = 0.0f;
}

// ---------------------------------------------------------------------------
// PTX helpers
// ---------------------------------------------------------------------------
__device__ __forceinline__ unsigned long long ffma2(unsigned long long a,
                                                    unsigned long long b,
                                                    unsigned long long c) {
    unsigned long long d;
    asm("fma.rn.f32x2 %0, %1, %2, %3;" : "=l"(d) : "l"(a), "l"(b), "l"(c));
    return d;
}
__device__ __forceinline__ unsigned long long pack2(float x) {
    unsigned long long r;
    unsigned u = __float_as_uint(x);
    asm("mov.b64 %0, {%1, %1};" : "=l"(r) : "r"(u));
    return r;
}
__device__ __forceinline__ void mbar_init(uint32_t mbar, uint32_t count) {
    asm volatile("mbarrier.init.shared.b64 [%0], %1;" :: "r"(mbar), "r"(count) : "memory");
}
__device__ __forceinline__ void mbar_expect_tx(uint32_t mbar, uint32_t bytes) {
    asm volatile("mbarrier.arrive.expect_tx.shared.b64 _, [%0], %1;"
                 :: "r"(mbar), "r"(bytes) : "memory");
}
__device__ __forceinline__ void mbar_wait(uint32_t mbar, uint32_t parity) {
    asm volatile(
        "{\n\t"
        ".reg .pred P;\n\t"
        "WAIT_%=:\n\t"
        "mbarrier.try_wait.parity.acquire.cta.shared::cta.b64 P, [%0], %1, 0x989680;\n\t"
        "@!P bra WAIT_%=;\n\t"
        "}"
        :: "r"(mbar), "r"(parity) : "memory");
}
// one 512B bulk copy: gmem row -> smem row, completion counted on mbar
__device__ __forceinline__ void cp_bulk(uint32_t dst, const void* src,
                                        uint32_t bytes, uint32_t mbar) {
    asm volatile(
        "cp.async.bulk.shared::cta.global.mbarrier::complete_tx::bytes [%0], [%1], %2, [%3];"
        :: "r"(dst), "l"(src), "r"(bytes), "r"(mbar) : "memory");
}

// ---------------------------------------------------------------------------
// Kernel B: 32-pixel tiles, bulk-copy k-streamed double buffer, 2 CTAs/SM
//   thread tile = 8b x 4o  (256 thr = 32 lp x 8 og)
// ---------------------------------------------------------------------------
__global__ void __launch_bounds__(256, 2) conv_kernel(
    const float* __restrict__ weight,   // [COUT][CIN][9]
    const float* __restrict__ bias,     // [COUT]
    const int*   __restrict__ neigh,    // [NPIX][9]
    float*       __restrict__ out)      // [B][COUT][NPIX]
{
    extern __shared__ char smem[];
    float* wS = (float*)smem;                      // [9][16][32] = 4608 f
    float* vB = wS + WS_FLOATS;                    // [2][32][CSTRIDE]
    int*   nS = (int*)(vB + VB_FLOATS);            // [288]
    float* oS = vB;                                // reused after compute

    const int tid = threadIdx.x;
    const int p0  = blockIdx.x * TILE_P;

    const uint32_t smem_u32 = (uint32_t)__cvta_generic_to_shared(smem);
    const uint32_t vB_u32   = smem_u32 + WS_FLOATS * 4;
    // mbarriers: 16B-aligned slot right after nS
    const uint32_t mb_base  = (smem_u32 + (WS_FLOATS + VB_FLOATS) * 4
                               + NS_INTS * 4 + 15) & ~15u;

    // stage weights as wS[k][c][o]
    for (int i = tid; i < WS_FLOATS; i += 256) {
        int k = i >> 9, rem = i & 511, c = rem >> 5, o = rem & 31;
        wS[i] = weight[o * 144 + c * 9 + k];
    }
    for (int i = tid; i < NS_INTS; i += 256) nS[i] = neigh[p0 * 9 + i];
    if (tid == 0) { mbar_init(mb_base, 1); mbar_init(mb_base + 8, 1); }
    __syncthreads();

    // chunk loader: 32 neighbour rows x 512B via 32 bulk copies
    auto load_chunk = [&](int k, int buf) {
        if (tid == 0) mbar_expect_tx(mb_base + buf * 8, TILE_P * 512);
        if (tid < TILE_P) {
            int idx = nS[tid * 9 + k];
            uint32_t dst = vB_u32 + (uint32_t)(buf * TILE_P + tid) * (CSTRIDE * 4);
            cp_bulk(dst, g_xt + (size_t)idx * BC, 512, mb_base + buf * 8);
        }
    };

    load_chunk(0, 0);

    // compute mapping: thread (lp, og) -> pixel p0+lp, outputs og*4..og*4+3
    const int lp = tid >> 3;
    const int og = tid & 7;

    unsigned long long acc[4][4];
    #pragma unroll
    for (int j = 0; j < 4; j++)
        #pragma unroll
        for (int i = 0; i < 4; i++) acc[j][i] = 0ULL;

    const float4* w4 = (const float4*)wS;
    int ph0 = 0, ph1 = 0;

    for (int k = 0; k < 9; k++) {
        if (k + 1 < 9) load_chunk(k + 1, (k + 1) & 1);

        const int buf = k & 1;
        if (buf == 0) { mbar_wait(mb_base, ph0);     ph0 ^= 1; }
        else          { mbar_wait(mb_base + 8, ph1); ph1 ^= 1; }

        const ulonglong2* v2 =
            (const ulonglong2*)(vB + (buf * TILE_P + lp) * CSTRIDE);

        #pragma unroll
        for (int c = 0; c < CIN; c++) {
            const int t = k * CIN + c;
            ulonglong2 va = v2[c * 2 + 0];   // (b0,b1),(b2,b3)
            ulonglong2 vb = v2[c * 2 + 1];   // (b4,b5),(b6,b7)
            float4 w = w4[t * 8 + og];
            unsigned long long wp0 = pack2(w.x), wp1 = pack2(w.y),
                               wp2 = pack2(w.z), wp3 = pack2(w.w);
            acc[0][0] = ffma2(va.x, wp0, acc[0][0]);
            acc[0][1] = ffma2(va.x, wp1, acc[0][1]);
            acc[0][2] = ffma2(va.x, wp2, acc[0][2]);
            acc[0][3] = ffma2(va.x, wp3, acc[0][3]);
            acc[1][0] = ffma2(va.y, wp0, acc[1][0]);
            acc[1][1] = ffma2(va.y, wp1, acc[1][1]);
            acc[1][2] = ffma2(va.y, wp2, acc[1][2]);
            acc[1][3] = ffma2(va.y, wp3, acc[1][3]);
            acc[2][0] = ffma2(vb.x, wp0, acc[2][0]);
            acc[2][1] = ffma2(vb.x, wp1, acc[2][1]);
            acc[2][2] = ffma2(vb.x, wp2, acc[2][2]);
            acc[2][3] = ffma2(vb.x, wp3, acc[2][3]);
            acc[3][0] = ffma2(vb.y, wp0, acc[3][0]);
            acc[3][1] = ffma2(vb.y, wp1, acc[3][1]);
            acc[3][2] = ffma2(vb.y, wp2, acc[3][2]);
            acc[3][3] = ffma2(vb.y, wp3, acc[3][3]);
        }
        // all threads must finish reading buf before the load for k+2
        // (issued at top of iteration k+1) overwrites it
        __syncthreads();
    }

    // epilogue: bias + stage to smem for coalesced global writes
    float4 bs = ((const float4*)bias)[og];
    float bi[4] = {bs.x, bs.y, bs.z, bs.w};
    #pragma unroll
    for (int j = 0; j < 4; j++) {
        #pragma unroll
        for (int i = 0; i < 4; i++) {
            float lo = __uint_as_float((unsigned)(acc[j][i] & 0xffffffffu));
            float hi = __uint_as_float((unsigned)(acc[j][i] >> 32));
            int o = og * 4 + i;
            oS[((2 * j)     * COUT + o) * (TILE_P + 1) + lp] = lo + bi[i];
            oS[((2 * j + 1) * COUT + o) * (TILE_P + 1) + lp] = hi + bi[i];
        }
    }
    __syncthreads();

    #pragma unroll
    for (int i = tid; i < B * COUT * TILE_P; i += 256) {   // 8192
        int row = i >> 5, col = i & 31;     // row = b*32+o
        out[row * NPIX + p0 + col] = oS[row * (TILE_P + 1) + col];
    }
}

// ---------------------------------------------------------------------------
extern "C" void kernel_launch(void* const* d_in, const int* in_sizes, int n_in,
                              void* d_out, int out_size) {
    const float* x      = (const float*)d_in[0];
    const float* weight = (const float*)d_in[1];
    const float* bias   = (const float*)d_in[2];
    const int*   neigh  = (const int*)d_in[3];
    float*       out    = (float*)d_out;

    cudaFuncSetAttribute(conv_kernel,
                         cudaFuncAttributeMaxDynamicSharedMemorySize,
                         SMEM_BYTES);

    transpose_kernel<<<NPIX / 32, 256>>>(x);
    conv_kernel<<<NPIX / TILE_P, 256, SMEM_BYTES>>>(weight, bias, neigh, out);
}